// round 5
// baseline (speedup 1.0000x reference)
#include <cuda_runtime.h>
#include <math.h>

#define B_   256
#define T_   64
#define IN_  600
#define H_   1000
#define G_   4000   // 4*H

// ---------------- device scratch (static globals: allocation-free) ----------
__device__ float g_xW[(size_t)B_ * T_ * G_];   // [(b*64+t)][p] permuted gate cols, incl bias1
__device__ float g_Wx1p[G_ * IN_];             // permuted W_ih1[:, 0:600]
__device__ float g_A1p[G_ * H_];               // permuted (W_ih1[:,600:1600] + W_hh1)
__device__ float g_W2ihp[G_ * H_];             // permuted W_ih2[:,600:1600]
__device__ float g_B2p[G_ * H_];               // permuted (W_ih2[:,1600:2600] + W_hh2)
__device__ float g_bias1p[G_];
__device__ float g_bias2p[G_];
__device__ float g_h1[2 * B_ * H_];            // ping-pong
__device__ float g_h2[2 * B_ * H_];            // ping-pong
__device__ float g_c1[B_ * H_];
__device__ float g_c2[B_ * H_];
__device__ float g_min[B_ * 2 * H_];           // [h1 | topic]
__device__ float g_m[B_ * G_];
__device__ float g_logits[B_ * H_];

// ---------------- weight prep (gate-interleaved permutation) ----------------
// permuted row p = j*4 + gate  <->  original row = gate*H_ + j
__global__ void prep_weights(const float* __restrict__ W_ih1, const float* __restrict__ W_hh1,
                             const float* __restrict__ b_ih1, const float* __restrict__ b_hh1,
                             const float* __restrict__ W_ih2, const float* __restrict__ W_hh2,
                             const float* __restrict__ b_ih2, const float* __restrict__ b_hh2) {
    int idx = blockIdx.x * blockDim.x + threadIdx.x;
    if (idx < G_ * H_) {
        int p = idx / H_;
        int k = idx - p * H_;
        int gate = p & 3, j = p >> 2;
        int orig = gate * H_ + j;
        g_A1p[idx]   = W_ih1[(size_t)orig * (IN_ + H_) + IN_ + k] + W_hh1[(size_t)orig * H_ + k];
        g_W2ihp[idx] = W_ih2[(size_t)orig * (IN_ + 2 * H_) + IN_ + k];
        g_B2p[idx]   = W_ih2[(size_t)orig * (IN_ + 2 * H_) + IN_ + H_ + k] + W_hh2[(size_t)orig * H_ + k];
    }
    if (idx < G_ * IN_) {
        int p = idx / IN_;
        int k = idx - p * IN_;
        int gate = p & 3, j = p >> 2;
        int orig = gate * H_ + j;
        g_Wx1p[idx] = W_ih1[(size_t)orig * (IN_ + H_) + k];
    }
    if (idx < G_) {
        int gate = idx & 3, j = idx >> 2;
        int orig = gate * H_ + j;
        g_bias1p[idx] = b_ih1[orig] + b_hh1[orig];
        g_bias2p[idx] = b_ih2[orig] + b_hh2[orig];
    }
}

__global__ void zero_states() {
    int idx = blockIdx.x * blockDim.x + threadIdx.x;
    if (idx < B_ * H_) {
        g_h1[idx] = 0.f; g_h1[B_ * H_ + idx] = 0.f;
        g_h2[idx] = 0.f; g_h2[B_ * H_ + idx] = 0.f;
        g_c1[idx] = 0.f; g_c2[idx] = 0.f;
    }
}

// ---------------- generic TN GEMM, optional fused LSTM epilogue -------------
// H matrices [M][K] row-major packed. W matrices [N][ldW] row-major (dot over K).
// mode 0: C[m][n] = base + acc   (base = initp[m*ldInit+n] or bias[n] or 0)
// mode 1: columns are gate-interleaved quads (j*4+gate); do LSTM pointwise,
//         update cState[m*H_+j] in place, write hOut[m*H_+j]. hOut must NOT
//         alias Ha/Hb (caller double-buffers).
#define BM 64
#define BN 128
#define BK 16

__device__ __forceinline__ float sigmoidf_(float x) { return 1.f / (1.f + expf(-x)); }

__global__ __launch_bounds__(256, 2)
void gemm_tn(float* __restrict__ C, int M, int N,
             const float* __restrict__ initp, int ldInit,
             const float* __restrict__ bias,
             const float* __restrict__ Ha, const float* __restrict__ Wa, int ldWa, int Ka,
             const float* __restrict__ Hb, const float* __restrict__ Wb, int ldWb, int Kb,
             int mode, float* __restrict__ hOut, float* __restrict__ cState) {
    __shared__ float As[BK][BM];
    __shared__ float Ws[BK][BN];

    const int tid = threadIdx.x;
    const int tx  = tid & 15;     // 0..15 (col group)
    const int ty  = tid >> 4;     // 0..15 (row group)
    const int row0 = blockIdx.y * BM;
    const int col0 = blockIdx.x * BN;

    float acc[4][8];
#pragma unroll
    for (int i = 0; i < 4; i++)
#pragma unroll
        for (int j = 0; j < 8; j++) acc[i][j] = 0.f;

    const int ar = tid >> 2;          // 0..63  (A row within tile)
    const int ak = (tid & 3) * 4;     // 0,4,8,12
    const int wn = tid >> 1;          // 0..127 (W row within tile)
    const int wk = (tid & 1) * 8;     // 0 or 8

    for (int seg = 0; seg < 2; seg++) {
        const float* Hm  = seg ? Hb  : Ha;
        const float* Wm  = seg ? Wb  : Wa;
        const int    ldW = seg ? ldWb : ldWa;
        const int    K   = seg ? Kb  : Ka;
        if (Hm == nullptr) continue;

        for (int k0 = 0; k0 < K; k0 += BK) {
            {
                float4 v = make_float4(0.f, 0.f, 0.f, 0.f);
                if (k0 + ak < K)
                    v = *(const float4*)(Hm + (size_t)(row0 + ar) * K + k0 + ak);
                As[ak + 0][ar] = v.x;
                As[ak + 1][ar] = v.y;
                As[ak + 2][ar] = v.z;
                As[ak + 3][ar] = v.w;
            }
            {
                const int n = col0 + wn;
#pragma unroll
                for (int q = 0; q < 2; q++) {
                    const int kk = wk + q * 4;
                    float4 v = make_float4(0.f, 0.f, 0.f, 0.f);
                    if (n < N && (k0 + kk) < K)
                        v = *(const float4*)(Wm + (size_t)n * ldW + k0 + kk);
                    Ws[kk + 0][wn] = v.x;
                    Ws[kk + 1][wn] = v.y;
                    Ws[kk + 2][wn] = v.z;
                    Ws[kk + 3][wn] = v.w;
                }
            }
            __syncthreads();
#pragma unroll
            for (int kk = 0; kk < BK; kk++) {
                const float4 a  = *(const float4*)&As[kk][ty * 4];
                const float4 b0 = *(const float4*)&Ws[kk][tx * 4];
                const float4 b1 = *(const float4*)&Ws[kk][64 + tx * 4];
                const float av[4] = {a.x, a.y, a.z, a.w};
                const float bv[8] = {b0.x, b0.y, b0.z, b0.w, b1.x, b1.y, b1.z, b1.w};
#pragma unroll
                for (int i = 0; i < 4; i++)
#pragma unroll
                    for (int j = 0; j < 8; j++)
                        acc[i][j] += av[i] * bv[j];
            }
            __syncthreads();
        }
    }

    if (mode == 0) {
#pragma unroll
        for (int i = 0; i < 4; i++) {
            const int m = row0 + ty * 4 + i;
#pragma unroll
            for (int j = 0; j < 8; j++) {
                const int n = col0 + ((j < 4) ? (tx * 4 + j) : (64 + tx * 4 + (j - 4)));
                if (n < N) {
                    float base = initp ? initp[(size_t)m * ldInit + n]
                                       : (bias ? bias[n] : 0.f);
                    C[(size_t)m * N + n] = base + acc[i][j];
                }
            }
        }
    } else {
        // fused LSTM epilogue: cols col0+tx*4+{0..3} / col0+64+tx*4+{0..3}
        // are gates i,f,g,o of units j0=(col0>>2)+tx and j1=(col0>>2)+16+tx.
        const int j0 = (col0 >> 2) + tx;
        const int j1 = (col0 >> 2) + 16 + tx;
#pragma unroll
        for (int i = 0; i < 4; i++) {
            const int m = row0 + ty * 4 + i;
#pragma unroll
            for (int q = 0; q < 2; q++) {
                const int jj = q ? j1 : j0;
                if (jj < H_) {
                    const int cbase = jj * 4;
                    float b0, b1, b2, b3;
                    if (initp) {
                        const float* ip = initp + (size_t)m * ldInit + cbase;
                        b0 = ip[0]; b1 = ip[1]; b2 = ip[2]; b3 = ip[3];
                    } else {
                        b0 = bias[cbase + 0]; b1 = bias[cbase + 1];
                        b2 = bias[cbase + 2]; b3 = bias[cbase + 3];
                    }
                    const float* a = &acc[i][q * 4];
                    float ig = sigmoidf_(a[0] + b0);
                    float fg = sigmoidf_(a[1] + b1);
                    float gg = tanhf    (a[2] + b2);
                    float og = sigmoidf_(a[3] + b3);
                    const size_t sidx = (size_t)m * H_ + jj;
                    float cn = fg * cState[sidx] + ig * gg;
                    cState[sidx] = cn;
                    hOut[sidx]  = og * tanhf(cn);
                }
            }
        }
    }
}

// ---------------- head ------------------------------------------------------
__global__ void build_min(const float* __restrict__ h1fin) {
    int idx = blockIdx.x * blockDim.x + threadIdx.x;
    if (idx >= B_ * 2 * H_) return;
    int b = idx / (2 * H_);
    int j = idx - b * 2 * H_;
    g_min[idx] = (j < H_) ? h1fin[b * H_ + j] : 0.f;
}

__global__ void scatter_topic(const int* __restrict__ hids) {
    int idx = blockIdx.x * blockDim.x + threadIdx.x;
    if (idx >= B_ * 5) return;
    int b = idx / 5;
    int id = hids[idx];
    if (id >= 0 && id < H_)
        g_min[(size_t)b * 2 * H_ + H_ + id] = 1.f;
}

// softmax over dim 0 (batch) for each of the 1000 columns
__global__ void softmax_dim0(float* __restrict__ out) {
    __shared__ float red[B_];
    const int j = blockIdx.x;
    const int b = threadIdx.x;      // blockDim == 256
    float v = g_logits[(size_t)b * H_ + j];
    red[b] = v;
    __syncthreads();
    for (int s = 128; s > 0; s >>= 1) {
        if (b < s) red[b] = fmaxf(red[b], red[b + s]);
        __syncthreads();
    }
    float mx = red[0];
    __syncthreads();
    float e = expf(v - mx);
    red[b] = e;
    __syncthreads();
    for (int s = 128; s > 0; s >>= 1) {
        if (b < s) red[b] += red[b + s];
        __syncthreads();
    }
    out[(size_t)b * H_ + j] = e / red[0];
}

__global__ void copy_out(float* __restrict__ out, int out_size,
                         const float* __restrict__ h1fin,
                         const float* __restrict__ h2fin) {
    int idx = blockIdx.x * blockDim.x + threadIdx.x;
    if (idx >= B_ * H_) return;
    if (out_size >= 5 * B_ * H_) {
        out[1 * B_ * H_ + idx] = h1fin[idx];
        out[2 * B_ * H_ + idx] = g_c1[idx];
        out[3 * B_ * H_ + idx] = h2fin[idx];
        out[4 * B_ * H_ + idx] = g_c2[idx];
    }
}

// ---------------- launch -----------------------------------------------------
extern "C" void kernel_launch(void* const* d_in, const int* in_sizes, int n_in,
                              void* d_out, int out_size) {
    const float* input = (const float*)d_in[0];   // (256,64,600)
    const int*   hids  = (const int*)  d_in[1];   // (256,5)
    const float* W_ih1 = (const float*)d_in[2];
    const float* W_hh1 = (const float*)d_in[3];
    const float* b_ih1 = (const float*)d_in[4];
    const float* b_hh1 = (const float*)d_in[5];
    const float* W_ih2 = (const float*)d_in[6];
    const float* W_hh2 = (const float*)d_in[7];
    const float* b_ih2 = (const float*)d_in[8];
    const float* b_hh2 = (const float*)d_in[9];
    const float* W1    = (const float*)d_in[10];
    const float* b1    = (const float*)d_in[11];
    const float* W2    = (const float*)d_in[12];
    const float* b2    = (const float*)d_in[13];
    float* out = (float*)d_out;

    float *xW, *Wx1p, *A1p, *W2ihp, *B2p, *bias1p, *bias2p;
    float *h1b, *h2b, *c1, *c2, *minb, *mbuf, *logits;
    cudaGetSymbolAddress((void**)&xW,     g_xW);
    cudaGetSymbolAddress((void**)&Wx1p,   g_Wx1p);
    cudaGetSymbolAddress((void**)&A1p,    g_A1p);
    cudaGetSymbolAddress((void**)&W2ihp,  g_W2ihp);
    cudaGetSymbolAddress((void**)&B2p,    g_B2p);
    cudaGetSymbolAddress((void**)&bias1p, g_bias1p);
    cudaGetSymbolAddress((void**)&bias2p, g_bias2p);
    cudaGetSymbolAddress((void**)&h1b,    g_h1);
    cudaGetSymbolAddress((void**)&h2b,    g_h2);
    cudaGetSymbolAddress((void**)&c1,     g_c1);
    cudaGetSymbolAddress((void**)&c2,     g_c2);
    cudaGetSymbolAddress((void**)&minb,   g_min);
    cudaGetSymbolAddress((void**)&mbuf,   g_m);
    cudaGetSymbolAddress((void**)&logits, g_logits);

    // 1) weight prep + state init
    prep_weights<<<(G_ * H_ + 255) / 256, 256>>>(W_ih1, W_hh1, b_ih1, b_hh1,
                                                 W_ih2, W_hh2, b_ih2, b_hh2);
    zero_states<<<(B_ * H_ + 255) / 256, 256>>>();

    // 2) precompute x-part for all timesteps (permuted cols, bias folded in)
    gemm_tn<<<dim3((G_ + BN - 1) / BN, (B_ * T_) / BM), 256>>>(
        xW, B_ * T_, G_,
        nullptr, 0, bias1p,
        input, Wx1p, IN_, IN_,
        nullptr, nullptr, 0, 0,
        0, nullptr, nullptr);

    // 3) recurrence (fused LSTM epilogues, ping-pong h buffers)
    const dim3 gstep((G_ + BN - 1) / BN, B_ / BM);
    const size_t SH = (size_t)B_ * H_;
    int cur = 0;
    for (int t = 0; t < T_; t++) {
        float* h1r = h1b + (size_t)cur * SH;        // read
        float* h1w = h1b + (size_t)(cur ^ 1) * SH;  // write
        float* h2r = h2b + (size_t)cur * SH;
        float* h2w = h2b + (size_t)(cur ^ 1) * SH;

        // gates1 = xW[t] + h1r @ A1p^T  -> h1w, c1
        gemm_tn<<<gstep, 256>>>(
            nullptr, B_, G_,
            xW + (size_t)t * G_, T_ * G_, nullptr,
            h1r, A1p, H_, H_,
            nullptr, nullptr, 0, 0,
            1, h1w, c1);
        // gates2 = bias2p + h1w @ W2ihp^T + h2r @ B2p^T -> h2w, c2
        gemm_tn<<<gstep, 256>>>(
            nullptr, B_, G_,
            nullptr, 0, bias2p,
            h1w, W2ihp, H_, H_,
            h2r, B2p, H_, H_,
            1, h2w, c2);
        cur ^= 1;
    }
    float* h1fin = h1b + (size_t)cur * SH;   // cur == 0 after 64 steps
    float* h2fin = h2b + (size_t)cur * SH;

    // 4) head
    build_min<<<(B_ * 2 * H_ + 255) / 256, 256>>>(h1fin);
    scatter_topic<<<(B_ * 5 + 255) / 256, 256>>>(hids);

    // m = [h1 | topic] @ W1^T + b1   (K=2000, N=4000)
    gemm_tn<<<dim3((G_ + BN - 1) / BN, B_ / BM), 256>>>(
        mbuf, B_, G_,
        nullptr, 0, b1,
        minb, W1, 2 * H_, 2 * H_,
        nullptr, nullptr, 0, 0,
        0, nullptr, nullptr);

    // logits = m @ W2^T + b2  (K=4000, N=1000)
    gemm_tn<<<dim3((H_ + BN - 1) / BN, B_ / BM), 256>>>(
        logits, B_, H_,
        nullptr, 0, b2,
        mbuf, W2, G_, G_,
        nullptr, nullptr, 0, 0,
        0, nullptr, nullptr);

    // 5) softmax over batch dim + state outputs
    softmax_dim0<<<H_, B_>>>(out);
    copy_out<<<(B_ * H_ + 255) / 256, 256>>>(out, out_size, h1fin, h2fin);
}

// round 8
// speedup vs baseline: 1.5683x; 1.5683x over previous
#include <cuda_runtime.h>
#include <cuda_bf16.h>
#include <math.h>
#include <stdint.h>

#define B_   256
#define T_   64
#define IN_  600
#define H_   1000
#define G_   4000   // 4*H
#define NP_  4096   // padded gate cols
#define KP_  1024   // padded K (H padded)
#define KC_  3072   // concat split K = 3*KP_

// ---------------- device scratch (static globals: allocation-free) ----------
__device__ float g_xW[(size_t)B_ * T_ * G_];
__device__ float g_Wx1p[G_ * IN_];
__device__ float g_A1p[G_ * H_];
__device__ float g_W2ihp[G_ * H_];
__device__ float g_B2p[G_ * H_];
__device__ float g_bias1p[G_];
__device__ float g_bias2p[G_];
// bf16 split-concat weights: [NP_][KC_]  cols = [hi | hi | lo]
__device__ __nv_bfloat16 g_A1cat[(size_t)NP_ * KC_];
__device__ __nv_bfloat16 g_W2cat[(size_t)NP_ * KC_];
__device__ __nv_bfloat16 g_B2cat[(size_t)NP_ * KC_];
// h split-concat activations, ping-pong: [2][B_][KC_]  cols = [hi | lo | hi]
__device__ __nv_bfloat16 g_h1cat[2 * (size_t)B_ * KC_];
__device__ __nv_bfloat16 g_h2cat[2 * (size_t)B_ * KC_];
__device__ float g_h1f[B_ * H_];
__device__ float g_h2f[B_ * H_];
__device__ float g_c1[B_ * H_];
__device__ float g_c2[B_ * H_];
__device__ float g_min[B_ * 2 * H_];
__device__ float g_m[B_ * G_];
__device__ float g_logits[B_ * H_];

// ---------------- weight prep (gate-interleaved permutation) ----------------
__global__ void prep_weights(const float* __restrict__ W_ih1, const float* __restrict__ W_hh1,
                             const float* __restrict__ b_ih1, const float* __restrict__ b_hh1,
                             const float* __restrict__ W_ih2, const float* __restrict__ W_hh2,
                             const float* __restrict__ b_ih2, const float* __restrict__ b_hh2) {
    int idx = blockIdx.x * blockDim.x + threadIdx.x;
    if (idx < G_ * H_) {
        int p = idx / H_;
        int k = idx - p * H_;
        int gate = p & 3, j = p >> 2;
        int orig = gate * H_ + j;
        g_A1p[idx]   = W_ih1[(size_t)orig * (IN_ + H_) + IN_ + k] + W_hh1[(size_t)orig * H_ + k];
        g_W2ihp[idx] = W_ih2[(size_t)orig * (IN_ + 2 * H_) + IN_ + k];
        g_B2p[idx]   = W_ih2[(size_t)orig * (IN_ + 2 * H_) + IN_ + H_ + k] + W_hh2[(size_t)orig * H_ + k];
    }
    if (idx < G_ * IN_) {
        int p = idx / IN_;
        int k = idx - p * IN_;
        int gate = p & 3, j = p >> 2;
        int orig = gate * H_ + j;
        g_Wx1p[idx] = W_ih1[(size_t)orig * (IN_ + H_) + k];
    }
    if (idx < G_) {
        int gate = idx & 3, j = idx >> 2;
        int orig = gate * H_ + j;
        g_bias1p[idx] = b_ih1[orig] + b_hh1[orig];
        g_bias2p[idx] = b_ih2[orig] + b_hh2[orig];
    }
}

// split fp32 weights -> bf16 concat [hi | hi | lo]; N pad 4096, K pad 1024
__global__ void split_weights() {
    size_t idx = (size_t)blockIdx.x * blockDim.x + threadIdx.x;
    if (idx >= (size_t)NP_ * KC_) return;
    int n  = (int)(idx / KC_);
    int kp = (int)(idx - (size_t)n * KC_);
    int seg = kp >> 10;
    int k   = kp & (KP_ - 1);
    bool valid = (n < G_) && (k < H_);
    size_t s = (size_t)n * H_ + k;
    float v1 = valid ? g_A1p[s]   : 0.f;
    float v2 = valid ? g_W2ihp[s] : 0.f;
    float v3 = valid ? g_B2p[s]   : 0.f;
    __nv_bfloat16 h1 = __float2bfloat16(v1);
    __nv_bfloat16 h2 = __float2bfloat16(v2);
    __nv_bfloat16 h3 = __float2bfloat16(v3);
    if (seg == 2) {
        g_A1cat[idx] = __float2bfloat16(v1 - __bfloat162float(h1));
        g_W2cat[idx] = __float2bfloat16(v2 - __bfloat162float(h2));
        g_B2cat[idx] = __float2bfloat16(v3 - __bfloat162float(h3));
    } else {
        g_A1cat[idx] = h1;
        g_W2cat[idx] = h2;
        g_B2cat[idx] = h3;
    }
}

__global__ void zero_states() {
    size_t idx = (size_t)blockIdx.x * blockDim.x + threadIdx.x;
    const size_t SC = (size_t)B_ * KC_;
    if (idx < SC) {
        __nv_bfloat16 z = __float2bfloat16(0.f);
        g_h1cat[idx] = z; g_h1cat[SC + idx] = z;
        g_h2cat[idx] = z; g_h2cat[SC + idx] = z;
    }
    if (idx < (size_t)B_ * H_) {
        g_h1f[idx] = 0.f; g_h2f[idx] = 0.f;
        g_c1[idx] = 0.f;  g_c2[idx] = 0.f;
    }
}

// ============ HMMA (mma.sync bf16) step GEMM with fused LSTM ================
// gates[m][p] = base + sum_seg A_s[m][:].W_s[p][:]   A:[256][3072] B:[4096][3072]
// CTA tile 128(M) x 64(N), 8 warps (4x2), warp tile 32x32, K-step 32, 4 stages.

#define MT   128
#define NT   64
#define KS   32
#define NSTG 4
#define ROWH 40                         // padded halfs per smem row (80B)
#define A_ST (MT * ROWH)                // halfs per A stage = 5120
#define B_ST (NT * ROWH)                // halfs per B stage = 2560
#define SMEM_HALFS (NSTG * (A_ST + B_ST))   // 30720 halfs = 61440 B
#define STEPS_PER_SEG (KC_ / KS)        // 96

__device__ __forceinline__ uint32_t smem_u32(const void* p) {
    uint32_t a;
    asm("{ .reg .u64 t; cvta.to.shared.u64 t, %1; cvt.u32.u64 %0, t; }" : "=r"(a) : "l"(p));
    return a;
}
__device__ __forceinline__ void cp_async16(uint32_t dst, const void* src) {
    asm volatile("cp.async.cg.shared.global [%0], [%1], 16;" :: "r"(dst), "l"(src));
}
__device__ __forceinline__ void cp_commit() { asm volatile("cp.async.commit_group;" ::: "memory"); }
template<int N> __device__ __forceinline__ void cp_wait() {
    asm volatile("cp.async.wait_group %0;" :: "n"(N) : "memory");
}
__device__ __forceinline__ void ldmat_x4(uint32_t a, uint32_t& r0, uint32_t& r1,
                                         uint32_t& r2, uint32_t& r3) {
    asm volatile("ldmatrix.sync.aligned.m8n8.x4.shared.b16 {%0,%1,%2,%3}, [%4];"
                 : "=r"(r0), "=r"(r1), "=r"(r2), "=r"(r3) : "r"(a));
}
__device__ __forceinline__ void mma16816(float* c, const uint32_t* a, uint32_t b0, uint32_t b1) {
    asm volatile(
        "mma.sync.aligned.m16n8k16.row.col.f32.bf16.bf16.f32 "
        "{%0,%1,%2,%3}, {%4,%5,%6,%7}, {%8,%9}, {%0,%1,%2,%3};"
        : "+f"(c[0]), "+f"(c[1]), "+f"(c[2]), "+f"(c[3])
        : "r"(a[0]), "r"(a[1]), "r"(a[2]), "r"(a[3]), "r"(b0), "r"(b1));
}
__device__ __forceinline__ float sigmoidf_(float x) { return 1.f / (1.f + expf(-x)); }

__global__ __launch_bounds__(256)
void tc_step(const __nv_bfloat16* __restrict__ A1s, const __nv_bfloat16* __restrict__ W1s,
             const __nv_bfloat16* __restrict__ A2s, const __nv_bfloat16* __restrict__ W2s,
             int nseg,
             const float* __restrict__ initp, long ldInit,
             const float* __restrict__ biasp,
             float* __restrict__ hfp, float* __restrict__ cst,
             __nv_bfloat16* __restrict__ hcat) {
    extern __shared__ __nv_bfloat16 sm[];
    const uint32_t sb = smem_u32(sm);
    const int tid  = threadIdx.x;
    const int wid  = tid >> 5;
    const int lane = tid & 31;
    const int row0 = blockIdx.y * MT;
    const int n0   = blockIdx.x * NT;
    const int S    = nseg * STEPS_PER_SEG;

    const int wm0 = (wid >> 1) * 32;    // warp M offset in tile
    const int wn0 = (wid & 1) * 32;     // warp N offset in tile

    float acc[2][4][4];
#pragma unroll
    for (int i = 0; i < 2; i++)
#pragma unroll
        for (int j = 0; j < 4; j++)
#pragma unroll
            for (int k = 0; k < 4; k++) acc[i][j][k] = 0.f;

    auto load_stage = [&](int sg) {
        const __nv_bfloat16* As = (sg < STEPS_PER_SEG) ? A1s : A2s;
        const __nv_bfloat16* Ws = (sg < STEPS_PER_SEG) ? W1s : W2s;
        const int kb = (sg < STEPS_PER_SEG ? sg : sg - STEPS_PER_SEG) * KS;
        const int st = sg & (NSTG - 1);
        const uint32_t ab = sb + (uint32_t)(st * A_ST) * 2;
        const uint32_t bb = sb + (uint32_t)((NSTG * A_ST + st * B_ST)) * 2;
        // A: 128 rows x 64B = 512 chunks of 16B; 2 per thread
#pragma unroll
        for (int t = 0; t < 2; t++) {
            int i = tid + t * 256;
            int r = i >> 2, c = i & 3;
            cp_async16(ab + (uint32_t)(r * 80 + c * 16),
                       (const char*)(As + (size_t)(row0 + r) * KC_ + kb) + c * 16);
        }
        // B: 64 rows x 64B = 256 chunks; 1 per thread
        {
            int r = tid >> 2, c = tid & 3;
            cp_async16(bb + (uint32_t)(r * 80 + c * 16),
                       (const char*)(Ws + (size_t)(n0 + r) * KC_ + kb) + c * 16);
        }
        cp_commit();
    };

    load_stage(0); load_stage(1); load_stage(2);

    for (int s = 0; s < S; s++) {
        const int rem = S - 1 - s;
        if (rem >= 2) cp_wait<2>(); else if (rem == 1) cp_wait<1>(); else cp_wait<0>();
        __syncthreads();

        const int nxt = s + 3;
        if (nxt < S) load_stage(nxt);

        const int st = s & (NSTG - 1);
        const uint32_t ab = sb + (uint32_t)(st * A_ST) * 2;
        const uint32_t bb = sb + (uint32_t)((NSTG * A_ST + st * B_ST)) * 2;

#pragma unroll
        for (int kk = 0; kk < KS; kk += 16) {
            uint32_t af[2][4], bf[2][4];
#pragma unroll
            for (int mi = 0; mi < 2; mi++) {
                uint32_t addr = ab + (uint32_t)((wm0 + mi * 16 + (lane & 15)) * 80
                                                + (kk + ((lane >> 4) << 3)) * 2);
                ldmat_x4(addr, af[mi][0], af[mi][1], af[mi][2], af[mi][3]);
            }
#pragma unroll
            for (int nh = 0; nh < 2; nh++) {
                uint32_t addr = bb + (uint32_t)((wn0 + nh * 16 + (lane & 15)) * 80
                                                + (kk + ((lane >> 4) << 3)) * 2);
                ldmat_x4(addr, bf[nh][0], bf[nh][1], bf[nh][2], bf[nh][3]);
            }
#pragma unroll
            for (int mi = 0; mi < 2; mi++)
#pragma unroll
                for (int nh = 0; nh < 2; nh++) {
                    mma16816(acc[mi][nh * 2 + 0], af[mi], bf[nh][0], bf[nh][2]);
                    mma16816(acc[mi][nh * 2 + 1], af[mi], bf[nh][1], bf[nh][3]);
                }
        }
    }

    // ---- epilogue: stage gates in smem (reuse stage buffers), fused LSTM ----
    __syncthreads();
    float* gsm = (float*)sm;            // 128 x 64 fp32 = 32KB < 61440B
#pragma unroll
    for (int mi = 0; mi < 2; mi++)
#pragma unroll
        for (int ni = 0; ni < 4; ni++) {
            int r = wm0 + mi * 16 + (lane >> 2);
            int cb = wn0 + ni * 8 + (lane & 3) * 2;
            gsm[r * 64 + cb]           = acc[mi][ni][0];
            gsm[r * 64 + cb + 1]       = acc[mi][ni][1];
            gsm[(r + 8) * 64 + cb]     = acc[mi][ni][2];
            gsm[(r + 8) * 64 + cb + 1] = acc[mi][ni][3];
        }
    __syncthreads();

    {
        const int ml = tid >> 1;            // 0..127
        const int u0 = (tid & 1) * 8;       // 0 or 8
        const int m  = row0 + ml;
        const int jb = n0 >> 2;
#pragma unroll
        for (int ui = 0; ui < 8; ui++) {
            const int u = u0 + ui;
            const int j = jb + u;
            if (j < H_) {
                const int p = n0 + u * 4;
                float b0, b1, b2, b3;
                if (initp) {
                    const float* ip = initp + (size_t)m * ldInit + p;
                    b0 = ip[0]; b1 = ip[1]; b2 = ip[2]; b3 = ip[3];
                } else {
                    b0 = biasp[p]; b1 = biasp[p + 1]; b2 = biasp[p + 2]; b3 = biasp[p + 3];
                }
                const float* g = gsm + ml * 64 + u * 4;
                float ig = sigmoidf_(g[0] + b0);
                float fg = sigmoidf_(g[1] + b1);
                float gg = tanhf    (g[2] + b2);
                float og = sigmoidf_(g[3] + b3);
                const size_t sidx = (size_t)m * H_ + j;
                float cn = fg * cst[sidx] + ig * gg;
                cst[sidx] = cn;
                float hv = og * tanhf(cn);
                hfp[sidx] = hv;
                __nv_bfloat16 hb = __float2bfloat16(hv);
                __nv_bfloat16 lb = __float2bfloat16(hv - __bfloat162float(hb));
                __nv_bfloat16* hc = hcat + (size_t)m * KC_;
                hc[j] = hb; hc[KP_ + j] = lb; hc[2 * KP_ + j] = hb;
            }
        }
    }
}

// ---------------- fp32 SIMT TN GEMM (precompute + head) ---------------------
#define BM 64
#define BN 128
#define BK 16

__global__ __launch_bounds__(256, 2)
void gemm_tn(float* __restrict__ C, int M, int N,
             const float* __restrict__ bias,
             const float* __restrict__ Ha, const float* __restrict__ Wa, int ldWa, int Ka) {
    __shared__ float As[BK][BM];
    __shared__ float Ws[BK][BN];

    const int tid = threadIdx.x;
    const int tx  = tid & 15;
    const int ty  = tid >> 4;
    const int row0 = blockIdx.y * BM;
    const int col0 = blockIdx.x * BN;

    float acc[4][8];
#pragma unroll
    for (int i = 0; i < 4; i++)
#pragma unroll
        for (int j = 0; j < 8; j++) acc[i][j] = 0.f;

    const int ar = tid >> 2;
    const int ak = (tid & 3) * 4;
    const int wn = tid >> 1;
    const int wk = (tid & 1) * 8;

    for (int k0 = 0; k0 < Ka; k0 += BK) {
        {
            float4 v = make_float4(0.f, 0.f, 0.f, 0.f);
            if (k0 + ak < Ka)
                v = *(const float4*)(Ha + (size_t)(row0 + ar) * Ka + k0 + ak);
            As[ak + 0][ar] = v.x; As[ak + 1][ar] = v.y;
            As[ak + 2][ar] = v.z; As[ak + 3][ar] = v.w;
        }
        {
            const int n = col0 + wn;
#pragma unroll
            for (int q = 0; q < 2; q++) {
                const int kk = wk + q * 4;
                float4 v = make_float4(0.f, 0.f, 0.f, 0.f);
                if (n < N && (k0 + kk) < Ka)
                    v = *(const float4*)(Wa + (size_t)n * ldWa + k0 + kk);
                Ws[kk + 0][wn] = v.x; Ws[kk + 1][wn] = v.y;
                Ws[kk + 2][wn] = v.z; Ws[kk + 3][wn] = v.w;
            }
        }
        __syncthreads();
#pragma unroll
        for (int kk = 0; kk < BK; kk++) {
            const float4 a  = *(const float4*)&As[kk][ty * 4];
            const float4 b0 = *(const float4*)&Ws[kk][tx * 4];
            const float4 b1 = *(const float4*)&Ws[kk][64 + tx * 4];
            const float av[4] = {a.x, a.y, a.z, a.w};
            const float bv[8] = {b0.x, b0.y, b0.z, b0.w, b1.x, b1.y, b1.z, b1.w};
#pragma unroll
            for (int i = 0; i < 4; i++)
#pragma unroll
                for (int j = 0; j < 8; j++)
                    acc[i][j] += av[i] * bv[j];
        }
        __syncthreads();
    }

#pragma unroll
    for (int i = 0; i < 4; i++) {
        const int m = row0 + ty * 4 + i;
#pragma unroll
        for (int j = 0; j < 8; j++) {
            const int n = col0 + ((j < 4) ? (tx * 4 + j) : (64 + tx * 4 + (j - 4)));
            if (n < N)
                C[(size_t)m * N + n] = (bias ? bias[n] : 0.f) + acc[i][j];
        }
    }
}

// ---------------- head ------------------------------------------------------
__global__ void build_min() {
    int idx = blockIdx.x * blockDim.x + threadIdx.x;
    if (idx >= B_ * 2 * H_) return;
    int b = idx / (2 * H_);
    int j = idx - b * 2 * H_;
    g_min[idx] = (j < H_) ? g_h1f[b * H_ + j] : 0.f;
}

__global__ void scatter_topic(const int* __restrict__ hids) {
    int idx = blockIdx.x * blockDim.x + threadIdx.x;
    if (idx >= B_ * 5) return;
    int b = idx / 5;
    int id = hids[idx];
    if (id >= 0 && id < H_)
        g_min[(size_t)b * 2 * H_ + H_ + id] = 1.f;
}

__global__ void softmax_dim0(float* __restrict__ out) {
    __shared__ float red[B_];
    const int j = blockIdx.x;
    const int b = threadIdx.x;
    float v = g_logits[(size_t)b * H_ + j];
    red[b] = v;
    __syncthreads();
    for (int s = 128; s > 0; s >>= 1) {
        if (b < s) red[b] = fmaxf(red[b], red[b + s]);
        __syncthreads();
    }
    float mx = red[0];
    __syncthreads();
    float e = expf(v - mx);
    red[b] = e;
    __syncthreads();
    for (int s = 128; s > 0; s >>= 1) {
        if (b < s) red[b] += red[b + s];
        __syncthreads();
    }
    out[(size_t)b * H_ + j] = e / red[0];
}

__global__ void copy_out(float* __restrict__ out, int out_size) {
    int idx = blockIdx.x * blockDim.x + threadIdx.x;
    if (idx >= B_ * H_) return;
    if (out_size >= 5 * B_ * H_) {
        out[1 * B_ * H_ + idx] = g_h1f[idx];
        out[2 * B_ * H_ + idx] = g_c1[idx];
        out[3 * B_ * H_ + idx] = g_h2f[idx];
        out[4 * B_ * H_ + idx] = g_c2[idx];
    }
}

// ---------------- launch -----------------------------------------------------
extern "C" void kernel_launch(void* const* d_in, const int* in_sizes, int n_in,
                              void* d_out, int out_size) {
    const float* input = (const float*)d_in[0];
    const int*   hids  = (const int*)  d_in[1];
    const float* W_ih1 = (const float*)d_in[2];
    const float* W_hh1 = (const float*)d_in[3];
    const float* b_ih1 = (const float*)d_in[4];
    const float* b_hh1 = (const float*)d_in[5];
    const float* W_ih2 = (const float*)d_in[6];
    const float* W_hh2 = (const float*)d_in[7];
    const float* b_ih2 = (const float*)d_in[8];
    const float* b_hh2 = (const float*)d_in[9];
    const float* W1    = (const float*)d_in[10];
    const float* b1    = (const float*)d_in[11];
    const float* W2    = (const float*)d_in[12];
    const float* b2    = (const float*)d_in[13];
    float* out = (float*)d_out;

    static bool s_attr = false;
    if (!s_attr) {
        cudaFuncSetAttribute(tc_step, cudaFuncAttributeMaxDynamicSharedMemorySize,
                             SMEM_HALFS * 2);
        s_attr = true;
    }

    float *xW, *Wx1p, *bias1p, *bias2p, *h1f, *h2f, *c1, *c2, *minb, *mbuf, *logits;
    __nv_bfloat16 *A1cat, *W2cat, *B2cat, *h1cat, *h2cat;
    cudaGetSymbolAddress((void**)&xW,     g_xW);
    cudaGetSymbolAddress((void**)&Wx1p,   g_Wx1p);
    cudaGetSymbolAddress((void**)&bias1p, g_bias1p);
    cudaGetSymbolAddress((void**)&bias2p, g_bias2p);
    cudaGetSymbolAddress((void**)&A1cat,  g_A1cat);
    cudaGetSymbolAddress((void**)&W2cat,  g_W2cat);
    cudaGetSymbolAddress((void**)&B2cat,  g_B2cat);
    cudaGetSymbolAddress((void**)&h1cat,  g_h1cat);
    cudaGetSymbolAddress((void**)&h2cat,  g_h2cat);
    cudaGetSymbolAddress((void**)&h1f,    g_h1f);
    cudaGetSymbolAddress((void**)&h2f,    g_h2f);
    cudaGetSymbolAddress((void**)&c1,     g_c1);
    cudaGetSymbolAddress((void**)&c2,     g_c2);
    cudaGetSymbolAddress((void**)&minb,   g_min);
    cudaGetSymbolAddress((void**)&mbuf,   g_m);
    cudaGetSymbolAddress((void**)&logits, g_logits);

    // 1) weight prep + split + state init
    prep_weights<<<(G_ * H_ + 255) / 256, 256>>>(W_ih1, W_hh1, b_ih1, b_hh1,
                                                 W_ih2, W_hh2, b_ih2, b_hh2);
    split_weights<<<(int)(((size_t)NP_ * KC_ + 255) / 256), 256>>>();
    zero_states<<<(B_ * KC_ + 255) / 256, 256>>>();

    // 2) precompute x-part for all timesteps (fp32 SIMT)
    gemm_tn<<<dim3((G_ + BN - 1) / BN, (B_ * T_) / BM), 256>>>(
        xW, B_ * T_, G_, bias1p, input, Wx1p, IN_, IN_);

    // 3) recurrence on HMMA tensor cores (split-bf16), ping-pong hcat buffers
    const dim3 tcg(NP_ / NT, B_ / MT);   // (64, 2) = 128 CTAs
    const size_t SC = (size_t)B_ * KC_;
    int cur = 0;
    for (int t = 0; t < T_; t++) {
        tc_step<<<tcg, 256, SMEM_HALFS * 2>>>(
            h1cat + (size_t)cur * SC, A1cat, nullptr, nullptr, 1,
            xW + (size_t)t * G_, (long)T_ * G_, nullptr,
            h1f, c1, h1cat + (size_t)(cur ^ 1) * SC);
        tc_step<<<tcg, 256, SMEM_HALFS * 2>>>(
            h1cat + (size_t)(cur ^ 1) * SC, W2cat,
            h2cat + (size_t)cur * SC, B2cat, 2,
            nullptr, 0, bias2p,
            h2f, c2, h2cat + (size_t)(cur ^ 1) * SC);
        cur ^= 1;
    }

    // 4) head (fp32 SIMT)
    build_min<<<(B_ * 2 * H_ + 255) / 256, 256>>>();
    scatter_topic<<<(B_ * 5 + 255) / 256, 256>>>(hids);

    gemm_tn<<<dim3((G_ + BN - 1) / BN, B_ / BM), 256>>>(
        mbuf, B_, G_, b1, minb, W1, 2 * H_, 2 * H_);
    gemm_tn<<<dim3((H_ + BN - 1) / BN, B_ / BM), 256>>>(
        logits, B_, H_, b2, mbuf, W2, G_, G_);

    // 5) softmax over batch dim + state outputs
    softmax_dim0<<<H_, B_>>>(out);
    copy_out<<<(B_ * H_ + 255) / 256, 256>>>(out, out_size);
}

// round 10
// speedup vs baseline: 1.9919x; 1.2701x over previous
#include <cuda_runtime.h>
#include <cuda_bf16.h>
#include <math.h>
#include <stdint.h>

#define B_   256
#define T_   64
#define IN_  600
#define H_   1000
#define G_   4000   // 4*H
#define NP_  4096   // padded gate cols
#define KP_  1024   // padded K (H padded)
#define KC_  3072   // concat split K for h = 3*KP_
#define KXP_ 640    // padded input K
#define KXC_ 1920   // concat split K for x = 3*KXP_

// ---------------- device scratch (static globals: allocation-free) ----------
__device__ float g_xW[(size_t)B_ * T_ * NP_];  // padded cols, bias folded
__device__ float g_Wx1p[G_ * IN_];
__device__ float g_A1p[G_ * H_];
__device__ float g_W2ihp[G_ * H_];
__device__ float g_B2p[G_ * H_];
__device__ float g_bias1p[NP_];
__device__ float g_bias2p[NP_];
// bf16 split-concat weights: [NP_][K]  cols = [hi | hi | lo]
__device__ __nv_bfloat16 g_A1cat[(size_t)NP_ * KC_];
__device__ __nv_bfloat16 g_W2cat[(size_t)NP_ * KC_];
__device__ __nv_bfloat16 g_B2cat[(size_t)NP_ * KC_];
__device__ __nv_bfloat16 g_Wxcat[(size_t)NP_ * KXC_];
// x split-concat: [16384][KXC_]  cols = [hi | lo | hi]
__device__ __nv_bfloat16 g_xcat[(size_t)B_ * T_ * KXC_];
// h split-concat activations, ping-pong: [2][B_][KC_]  cols = [hi | lo | hi]
__device__ __nv_bfloat16 g_h1cat[2 * (size_t)B_ * KC_];
__device__ __nv_bfloat16 g_h2cat[2 * (size_t)B_ * KC_];
__device__ float g_h1f[B_ * H_];
__device__ float g_h2f[B_ * H_];
__device__ float g_c1[B_ * H_];
__device__ float g_c2[B_ * H_];
__device__ float g_min[B_ * 2 * H_];
__device__ float g_m[B_ * G_];
__device__ float g_logits[B_ * H_];

// ---------------- weight prep (gate-interleaved permutation) ----------------
__global__ void prep_weights(const float* __restrict__ W_ih1, const float* __restrict__ W_hh1,
                             const float* __restrict__ b_ih1, const float* __restrict__ b_hh1,
                             const float* __restrict__ W_ih2, const float* __restrict__ W_hh2,
                             const float* __restrict__ b_ih2, const float* __restrict__ b_hh2) {
    int idx = blockIdx.x * blockDim.x + threadIdx.x;
    if (idx < G_ * H_) {
        int p = idx / H_;
        int k = idx - p * H_;
        int gate = p & 3, j = p >> 2;
        int orig = gate * H_ + j;
        g_A1p[idx]   = W_ih1[(size_t)orig * (IN_ + H_) + IN_ + k] + W_hh1[(size_t)orig * H_ + k];
        g_W2ihp[idx] = W_ih2[(size_t)orig * (IN_ + 2 * H_) + IN_ + k];
        g_B2p[idx]   = W_ih2[(size_t)orig * (IN_ + 2 * H_) + IN_ + H_ + k] + W_hh2[(size_t)orig * H_ + k];
    }
    if (idx < G_ * IN_) {
        int p = idx / IN_;
        int k = idx - p * IN_;
        int gate = p & 3, j = p >> 2;
        int orig = gate * H_ + j;
        g_Wx1p[idx] = W_ih1[(size_t)orig * (IN_ + H_) + k];
    }
    if (idx < NP_) {
        if (idx < G_) {
            int gate = idx & 3, j = idx >> 2;
            int orig = gate * H_ + j;
            g_bias1p[idx] = b_ih1[orig] + b_hh1[orig];
            g_bias2p[idx] = b_ih2[orig] + b_hh2[orig];
        } else {
            g_bias1p[idx] = 0.f;
            g_bias2p[idx] = 0.f;
        }
    }
}

// split fp32 h-weights -> bf16 concat [hi | hi | lo]; N pad 4096, K pad 1024
__global__ void split_weights() {
    size_t idx = (size_t)blockIdx.x * blockDim.x + threadIdx.x;
    if (idx >= (size_t)NP_ * KC_) return;
    int n  = (int)(idx / KC_);
    int kp = (int)(idx - (size_t)n * KC_);
    int seg = kp >> 10;
    int k   = kp & (KP_ - 1);
    bool valid = (n < G_) && (k < H_);
    size_t s = (size_t)n * H_ + k;
    float v1 = valid ? g_A1p[s]   : 0.f;
    float v2 = valid ? g_W2ihp[s] : 0.f;
    float v3 = valid ? g_B2p[s]   : 0.f;
    __nv_bfloat16 h1 = __float2bfloat16(v1);
    __nv_bfloat16 h2 = __float2bfloat16(v2);
    __nv_bfloat16 h3 = __float2bfloat16(v3);
    if (seg == 2) {
        g_A1cat[idx] = __float2bfloat16(v1 - __bfloat162float(h1));
        g_W2cat[idx] = __float2bfloat16(v2 - __bfloat162float(h2));
        g_B2cat[idx] = __float2bfloat16(v3 - __bfloat162float(h3));
    } else {
        g_A1cat[idx] = h1;
        g_W2cat[idx] = h2;
        g_B2cat[idx] = h3;
    }
}

// split fp32 x-weights -> bf16 concat [hi | hi | lo]; K pad 640
__global__ void split_wx() {
    size_t idx = (size_t)blockIdx.x * blockDim.x + threadIdx.x;
    if (idx >= (size_t)NP_ * KXC_) return;
    int n  = (int)(idx / KXC_);
    int kp = (int)(idx - (size_t)n * KXC_);
    int seg = kp / KXP_;
    int k   = kp - seg * KXP_;
    bool valid = (n < G_) && (k < IN_);
    float v = valid ? g_Wx1p[(size_t)n * IN_ + k] : 0.f;
    __nv_bfloat16 h = __float2bfloat16(v);
    g_Wxcat[idx] = (seg == 2) ? __float2bfloat16(v - __bfloat162float(h)) : h;
}

// split input x -> bf16 concat [hi | lo | hi]
__global__ void split_x(const float* __restrict__ input) {
    size_t idx = (size_t)blockIdx.x * blockDim.x + threadIdx.x;
    if (idx >= (size_t)B_ * T_ * KXC_) return;
    int r  = (int)(idx / KXC_);
    int kp = (int)(idx - (size_t)r * KXC_);
    int seg = kp / KXP_;
    int k   = kp - seg * KXP_;
    float v = (k < IN_) ? input[(size_t)r * IN_ + k] : 0.f;
    __nv_bfloat16 h = __float2bfloat16(v);
    g_xcat[idx] = (seg == 1) ? __float2bfloat16(v - __bfloat162float(h)) : h;
}

__global__ void zero_states() {
    size_t idx = (size_t)blockIdx.x * blockDim.x + threadIdx.x;
    const size_t SC = (size_t)B_ * KC_;
    if (idx < SC) {
        __nv_bfloat16 z = __float2bfloat16(0.f);
        g_h1cat[idx] = z; g_h1cat[SC + idx] = z;
        g_h2cat[idx] = z; g_h2cat[SC + idx] = z;
    }
    if (idx < (size_t)B_ * H_) {
        g_h1f[idx] = 0.f; g_h2f[idx] = 0.f;
        g_c1[idx] = 0.f;  g_c2[idx] = 0.f;
    }
}

// ============ unified HMMA GEMM: plain-store OR fused-LSTM epilogue =========
// CTA tile 128(M) x 64(N), 8 warps (4x2), warp tile 32x32, K-stage 64, 4 stages.
// (Resubmission of R9: bench infra failed before execution; kernel unchanged.)

#define MT   128
#define NT   64
#define KS   64
#define NSTG 4
#define ROWH 72                         // padded halfs per smem row (144B)
#define A_ST (MT * ROWH)                // 9216 halfs
#define B_ST (NT * ROWH)                // 4608 halfs
#define SMEM_BYTES (NSTG * (A_ST + B_ST) * 2)   // 110592 B

__device__ __forceinline__ uint32_t smem_u32(const void* p) {
    uint32_t a;
    asm("{ .reg .u64 t; cvta.to.shared.u64 t, %1; cvt.u32.u64 %0, t; }" : "=r"(a) : "l"(p));
    return a;
}
__device__ __forceinline__ void cp_async16(uint32_t dst, const void* src) {
    asm volatile("cp.async.cg.shared.global [%0], [%1], 16;" :: "r"(dst), "l"(src));
}
__device__ __forceinline__ void cp_commit() { asm volatile("cp.async.commit_group;" ::: "memory"); }
template<int N> __device__ __forceinline__ void cp_wait() {
    asm volatile("cp.async.wait_group %0;" :: "n"(N) : "memory");
}
__device__ __forceinline__ void ldmat_x4(uint32_t a, uint32_t& r0, uint32_t& r1,
                                         uint32_t& r2, uint32_t& r3) {
    asm volatile("ldmatrix.sync.aligned.m8n8.x4.shared.b16 {%0,%1,%2,%3}, [%4];"
                 : "=r"(r0), "=r"(r1), "=r"(r2), "=r"(r3) : "r"(a));
}
__device__ __forceinline__ void mma16816(float* c, const uint32_t* a, uint32_t b0, uint32_t b1) {
    asm volatile(
        "mma.sync.aligned.m16n8k16.row.col.f32.bf16.bf16.f32 "
        "{%0,%1,%2,%3}, {%4,%5,%6,%7}, {%8,%9}, {%0,%1,%2,%3};"
        : "+f"(c[0]), "+f"(c[1]), "+f"(c[2]), "+f"(c[3])
        : "r"(a[0]), "r"(a[1]), "r"(a[2]), "r"(a[3]), "r"(b0), "r"(b1));
}
__device__ __forceinline__ float sigmoidf_(float x) { return 1.f / (1.f + expf(-x)); }

// A matrices [*, ld], W matrices [NP_, ld]. S = nseg * spseg stages of K=64.
// outp != null : outp[m][NP_] = acc + biasp  (plain store)
// outp == null : fused LSTM epilogue (initp or biasp base; update cst, hfp, hcat)
__global__ __launch_bounds__(256)
void tc_gemm(const __nv_bfloat16* __restrict__ A1s, const __nv_bfloat16* __restrict__ W1s,
             const __nv_bfloat16* __restrict__ A2s, const __nv_bfloat16* __restrict__ W2s,
             int nseg, int spseg, int ld,
             const float* __restrict__ initp, long ldInit,
             const float* __restrict__ biasp,
             float* __restrict__ hfp, float* __restrict__ cst,
             __nv_bfloat16* __restrict__ hcat, float* __restrict__ outp) {
    extern __shared__ __nv_bfloat16 sm[];
    const uint32_t sb = smem_u32(sm);
    const int tid  = threadIdx.x;
    const int wid  = tid >> 5;
    const int lane = tid & 31;
    const int row0 = blockIdx.y * MT;
    const int n0   = blockIdx.x * NT;
    const int S    = nseg * spseg;

    const int wm0 = (wid >> 1) * 32;
    const int wn0 = (wid & 1) * 32;

    float acc[2][4][4];
#pragma unroll
    for (int i = 0; i < 2; i++)
#pragma unroll
        for (int j = 0; j < 4; j++)
#pragma unroll
            for (int k = 0; k < 4; k++) acc[i][j][k] = 0.f;

    auto load_stage = [&](int sg) {
        const __nv_bfloat16* As = (sg < spseg) ? A1s : A2s;
        const __nv_bfloat16* Ws = (sg < spseg) ? W1s : W2s;
        const int kb = (sg < spseg ? sg : sg - spseg) * KS;
        const int st = sg & (NSTG - 1);
        const uint32_t ab = sb + (uint32_t)(st * A_ST) * 2;
        const uint32_t bb = sb + (uint32_t)((NSTG * A_ST + st * B_ST)) * 2;
        // A: 128 rows x 128B = 1024 chunks of 16B; 4 per thread
#pragma unroll
        for (int t = 0; t < 4; t++) {
            int i = tid + t * 256;
            int r = i >> 3, c = i & 7;
            cp_async16(ab + (uint32_t)(r * 144 + c * 16),
                       (const char*)(As + (size_t)(row0 + r) * ld + kb) + c * 16);
        }
        // B: 64 rows x 128B = 512 chunks; 2 per thread
#pragma unroll
        for (int t = 0; t < 2; t++) {
            int i = tid + t * 256;
            int r = i >> 3, c = i & 7;
            cp_async16(bb + (uint32_t)(r * 144 + c * 16),
                       (const char*)(Ws + (size_t)(n0 + r) * ld + kb) + c * 16);
        }
        cp_commit();
    };

    load_stage(0); load_stage(1); load_stage(2);

    for (int s = 0; s < S; s++) {
        const int rem = S - 1 - s;
        if (rem >= 2) cp_wait<2>(); else if (rem == 1) cp_wait<1>(); else cp_wait<0>();
        __syncthreads();

        const int nxt = s + 3;
        if (nxt < S) load_stage(nxt);

        const int st = s & (NSTG - 1);
        const uint32_t ab = sb + (uint32_t)(st * A_ST) * 2;
        const uint32_t bb = sb + (uint32_t)((NSTG * A_ST + st * B_ST)) * 2;

#pragma unroll
        for (int kk = 0; kk < KS; kk += 16) {
            uint32_t af[2][4], bf[2][4];
#pragma unroll
            for (int mi = 0; mi < 2; mi++) {
                uint32_t addr = ab + (uint32_t)((wm0 + mi * 16 + (lane & 15)) * 144
                                                + (kk + ((lane >> 4) << 3)) * 2);
                ldmat_x4(addr, af[mi][0], af[mi][1], af[mi][2], af[mi][3]);
            }
#pragma unroll
            for (int nh = 0; nh < 2; nh++) {
                uint32_t addr = bb + (uint32_t)((wn0 + nh * 16 + (lane & 15)) * 144
                                                + (kk + ((lane >> 4) << 3)) * 2);
                ldmat_x4(addr, bf[nh][0], bf[nh][1], bf[nh][2], bf[nh][3]);
            }
#pragma unroll
            for (int mi = 0; mi < 2; mi++)
#pragma unroll
                for (int nh = 0; nh < 2; nh++) {
                    mma16816(acc[mi][nh * 2 + 0], af[mi], bf[nh][0], bf[nh][2]);
                    mma16816(acc[mi][nh * 2 + 1], af[mi], bf[nh][1], bf[nh][3]);
                }
        }
    }

    // ---- stage accumulators in smem (reuse stage buffers) ----
    __syncthreads();
    float* gsm = (float*)sm;            // 128 x 64 fp32 = 32KB < SMEM_BYTES
#pragma unroll
    for (int mi = 0; mi < 2; mi++)
#pragma unroll
        for (int ni = 0; ni < 4; ni++) {
            int r = wm0 + mi * 16 + (lane >> 2);
            int cb = wn0 + ni * 8 + (lane & 3) * 2;
            gsm[r * 64 + cb]           = acc[mi][ni][0];
            gsm[r * 64 + cb + 1]       = acc[mi][ni][1];
            gsm[(r + 8) * 64 + cb]     = acc[mi][ni][2];
            gsm[(r + 8) * 64 + cb + 1] = acc[mi][ni][3];
        }
    __syncthreads();

    if (outp) {
        // plain store: out[m][n0..n0+63] = acc + bias (row stride NP_)
        const int r = tid >> 1;
        const int half = tid & 1;
        float* op = outp + (size_t)(row0 + r) * NP_ + n0 + half * 32;
        const float* gp = gsm + r * 64 + half * 32;
        const float* bp = biasp + n0 + half * 32;
#pragma unroll
        for (int q = 0; q < 8; q++) {
            float4 v;
            v.x = gp[q * 4 + 0] + bp[q * 4 + 0];
            v.y = gp[q * 4 + 1] + bp[q * 4 + 1];
            v.z = gp[q * 4 + 2] + bp[q * 4 + 2];
            v.w = gp[q * 4 + 3] + bp[q * 4 + 3];
            *(float4*)(op + q * 4) = v;
        }
    } else {
        const int ml = tid >> 1;
        const int u0 = (tid & 1) * 8;
        const int m  = row0 + ml;
        const int jb = n0 >> 2;
#pragma unroll
        for (int ui = 0; ui < 8; ui++) {
            const int u = u0 + ui;
            const int j = jb + u;
            if (j < H_) {
                const int p = n0 + u * 4;
                float b0, b1, b2, b3;
                if (initp) {
                    const float* ip = initp + (size_t)m * ldInit + p;
                    b0 = ip[0]; b1 = ip[1]; b2 = ip[2]; b3 = ip[3];
                } else {
                    b0 = biasp[p]; b1 = biasp[p + 1]; b2 = biasp[p + 2]; b3 = biasp[p + 3];
                }
                const float* g = gsm + ml * 64 + u * 4;
                float ig = sigmoidf_(g[0] + b0);
                float fg = sigmoidf_(g[1] + b1);
                float gg = tanhf    (g[2] + b2);
                float og = sigmoidf_(g[3] + b3);
                const size_t sidx = (size_t)m * H_ + j;
                float cn = fg * cst[sidx] + ig * gg;
                cst[sidx] = cn;
                float hv = og * tanhf(cn);
                hfp[sidx] = hv;
                __nv_bfloat16 hb = __float2bfloat16(hv);
                __nv_bfloat16 lb = __float2bfloat16(hv - __bfloat162float(hb));
                __nv_bfloat16* hc = hcat + (size_t)m * KC_;
                hc[j] = hb; hc[KP_ + j] = lb; hc[2 * KP_ + j] = hb;
            }
        }
    }
}

// ---------------- fp32 SIMT TN GEMM (head) ----------------------------------
#define BM 64
#define BN 128
#define BK 16

__global__ __launch_bounds__(256, 2)
void gemm_tn(float* __restrict__ C, int M, int N,
             const float* __restrict__ bias,
             const float* __restrict__ Ha, const float* __restrict__ Wa, int ldWa, int Ka) {
    __shared__ float As[BK][BM];
    __shared__ float Ws[BK][BN];

    const int tid = threadIdx.x;
    const int tx  = tid & 15;
    const int ty  = tid >> 4;
    const int row0 = blockIdx.y * BM;
    const int col0 = blockIdx.x * BN;

    float acc[4][8];
#pragma unroll
    for (int i = 0; i < 4; i++)
#pragma unroll
        for (int j = 0; j < 8; j++) acc[i][j] = 0.f;

    const int ar = tid >> 2;
    const int ak = (tid & 3) * 4;
    const int wn = tid >> 1;
    const int wk = (tid & 1) * 8;

    for (int k0 = 0; k0 < Ka; k0 += BK) {
        {
            float4 v = make_float4(0.f, 0.f, 0.f, 0.f);
            if (k0 + ak < Ka)
                v = *(const float4*)(Ha + (size_t)(row0 + ar) * Ka + k0 + ak);
            As[ak + 0][ar] = v.x; As[ak + 1][ar] = v.y;
            As[ak + 2][ar] = v.z; As[ak + 3][ar] = v.w;
        }
        {
            const int n = col0 + wn;
#pragma unroll
            for (int q = 0; q < 2; q++) {
                const int kk = wk + q * 4;
                float4 v = make_float4(0.f, 0.f, 0.f, 0.f);
                if (n < N && (k0 + kk) < Ka)
                    v = *(const float4*)(Wa + (size_t)n * ldWa + k0 + kk);
                Ws[kk + 0][wn] = v.x; Ws[kk + 1][wn] = v.y;
                Ws[kk + 2][wn] = v.z; Ws[kk + 3][wn] = v.w;
            }
        }
        __syncthreads();
#pragma unroll
        for (int kk = 0; kk < BK; kk++) {
            const float4 a  = *(const float4*)&As[kk][ty * 4];
            const float4 b0 = *(const float4*)&Ws[kk][tx * 4];
            const float4 b1 = *(const float4*)&Ws[kk][64 + tx * 4];
            const float av[4] = {a.x, a.y, a.z, a.w};
            const float bv[8] = {b0.x, b0.y, b0.z, b0.w, b1.x, b1.y, b1.z, b1.w};
#pragma unroll
            for (int i = 0; i < 4; i++)
#pragma unroll
                for (int j = 0; j < 8; j++)
                    acc[i][j] += av[i] * bv[j];
        }
        __syncthreads();
    }

#pragma unroll
    for (int i = 0; i < 4; i++) {
        const int m = row0 + ty * 4 + i;
#pragma unroll
        for (int j = 0; j < 8; j++) {
            const int n = col0 + ((j < 4) ? (tx * 4 + j) : (64 + tx * 4 + (j - 4)));
            if (n < N)
                C[(size_t)m * N + n] = (bias ? bias[n] : 0.f) + acc[i][j];
        }
    }
}

// ---------------- head ------------------------------------------------------
__global__ void build_min() {
    int idx = blockIdx.x * blockDim.x + threadIdx.x;
    if (idx >= B_ * 2 * H_) return;
    int b = idx / (2 * H_);
    int j = idx - b * 2 * H_;
    g_min[idx] = (j < H_) ? g_h1f[b * H_ + j] : 0.f;
}

__global__ void scatter_topic(const int* __restrict__ hids) {
    int idx = blockIdx.x * blockDim.x + threadIdx.x;
    if (idx >= B_ * 5) return;
    int b = idx / 5;
    int id = hids[idx];
    if (id >= 0 && id < H_)
        g_min[(size_t)b * 2 * H_ + H_ + id] = 1.f;
}

__global__ void softmax_dim0(float* __restrict__ out) {
    __shared__ float red[B_];
    const int j = blockIdx.x;
    const int b = threadIdx.x;
    float v = g_logits[(size_t)b * H_ + j];
    red[b] = v;
    __syncthreads();
    for (int s = 128; s > 0; s >>= 1) {
        if (b < s) red[b] = fmaxf(red[b], red[b + s]);
        __syncthreads();
    }
    float mx = red[0];
    __syncthreads();
    float e = expf(v - mx);
    red[b] = e;
    __syncthreads();
    for (int s = 128; s > 0; s >>= 1) {
        if (b < s) red[b] += red[b + s];
        __syncthreads();
    }
    out[(size_t)b * H_ + j] = e / red[0];
}

__global__ void copy_out(float* __restrict__ out, int out_size) {
    int idx = blockIdx.x * blockDim.x + threadIdx.x;
    if (idx >= B_ * H_) return;
    if (out_size >= 5 * B_ * H_) {
        out[1 * B_ * H_ + idx] = g_h1f[idx];
        out[2 * B_ * H_ + idx] = g_c1[idx];
        out[3 * B_ * H_ + idx] = g_h2f[idx];
        out[4 * B_ * H_ + idx] = g_c2[idx];
    }
}

// ---------------- launch -----------------------------------------------------
extern "C" void kernel_launch(void* const* d_in, const int* in_sizes, int n_in,
                              void* d_out, int out_size) {
    const float* input = (const float*)d_in[0];
    const int*   hids  = (const int*)  d_in[1];
    const float* W_ih1 = (const float*)d_in[2];
    const float* W_hh1 = (const float*)d_in[3];
    const float* b_ih1 = (const float*)d_in[4];
    const float* b_hh1 = (const float*)d_in[5];
    const float* W_ih2 = (const float*)d_in[6];
    const float* W_hh2 = (const float*)d_in[7];
    const float* b_ih2 = (const float*)d_in[8];
    const float* b_hh2 = (const float*)d_in[9];
    const float* W1    = (const float*)d_in[10];
    const float* b1    = (const float*)d_in[11];
    const float* W2    = (const float*)d_in[12];
    const float* b2    = (const float*)d_in[13];
    float* out = (float*)d_out;

    static bool s_attr = false;
    if (!s_attr) {
        cudaFuncSetAttribute(tc_gemm, cudaFuncAttributeMaxDynamicSharedMemorySize, SMEM_BYTES);
        s_attr = true;
    }

    float *xW, *bias1p, *bias2p, *h1f, *h2f, *c1, *c2, *minb, *mbuf, *logits;
    __nv_bfloat16 *A1cat, *W2cat, *B2cat, *Wxcat, *xcat, *h1cat, *h2cat;
    cudaGetSymbolAddress((void**)&xW,     g_xW);
    cudaGetSymbolAddress((void**)&bias1p, g_bias1p);
    cudaGetSymbolAddress((void**)&bias2p, g_bias2p);
    cudaGetSymbolAddress((void**)&A1cat,  g_A1cat);
    cudaGetSymbolAddress((void**)&W2cat,  g_W2cat);
    cudaGetSymbolAddress((void**)&B2cat,  g_B2cat);
    cudaGetSymbolAddress((void**)&Wxcat,  g_Wxcat);
    cudaGetSymbolAddress((void**)&xcat,   g_xcat);
    cudaGetSymbolAddress((void**)&h1cat,  g_h1cat);
    cudaGetSymbolAddress((void**)&h2cat,  g_h2cat);
    cudaGetSymbolAddress((void**)&h1f,    g_h1f);
    cudaGetSymbolAddress((void**)&h2f,    g_h2f);
    cudaGetSymbolAddress((void**)&c1,     g_c1);
    cudaGetSymbolAddress((void**)&c2,     g_c2);
    cudaGetSymbolAddress((void**)&minb,   g_min);
    cudaGetSymbolAddress((void**)&mbuf,   g_m);
    cudaGetSymbolAddress((void**)&logits, g_logits);

    // 1) weight prep + splits + state init
    prep_weights<<<(G_ * H_ + 255) / 256, 256>>>(W_ih1, W_hh1, b_ih1, b_hh1,
                                                 W_ih2, W_hh2, b_ih2, b_hh2);
    split_weights<<<(int)(((size_t)NP_ * KC_ + 255) / 256), 256>>>();
    split_wx<<<(int)(((size_t)NP_ * KXC_ + 255) / 256), 256>>>();
    split_x<<<(int)(((size_t)B_ * T_ * KXC_ + 255) / 256), 256>>>(input);
    zero_states<<<(B_ * KC_ + 255) / 256, 256>>>();

    // 2) precompute x-part via HMMA: xW[16384][4096] = xcat @ Wxcat^T + bias1p
    tc_gemm<<<dim3(NP_ / NT, (B_ * T_) / MT), 256, SMEM_BYTES>>>(
        xcat, Wxcat, nullptr, nullptr, 1, KXC_ / KS, KXC_,
        nullptr, 0, bias1p,
        nullptr, nullptr, nullptr, xW);

    // 3) recurrence on HMMA (split-bf16), ping-pong hcat buffers
    const dim3 tcg(NP_ / NT, B_ / MT);   // (64, 2) = 128 CTAs
    const size_t SC = (size_t)B_ * KC_;
    int cur = 0;
    for (int t = 0; t < T_; t++) {
        tc_gemm<<<tcg, 256, SMEM_BYTES>>>(
            h1cat + (size_t)cur * SC, A1cat, nullptr, nullptr, 1, KC_ / KS, KC_,
            xW + (size_t)t * NP_, (long)T_ * NP_, nullptr,
            h1f, c1, h1cat + (size_t)(cur ^ 1) * SC, nullptr);
        tc_gemm<<<tcg, 256, SMEM_BYTES>>>(
            h1cat + (size_t)(cur ^ 1) * SC, W2cat,
            h2cat + (size_t)cur * SC, B2cat, 2, KC_ / KS, KC_,
            nullptr, 0, bias2p,
            h2f, c2, h2cat + (size_t)(cur ^ 1) * SC, nullptr);
        cur ^= 1;
    }

    // 4) head (fp32 SIMT)
    build_min<<<(B_ * 2 * H_ + 255) / 256, 256>>>();
    scatter_topic<<<(B_ * 5 + 255) / 256, 256>>>(hids);

    gemm_tn<<<dim3((G_ + BN - 1) / BN, B_ / BM), 256>>>(
        mbuf, B_, G_, b1, minb, W1, 2 * H_, 2 * H_);
    gemm_tn<<<dim3((H_ + BN - 1) / BN, B_ / BM), 256>>>(
        logits, B_, H_, b2, mbuf, W2, G_, G_);

    // 5) softmax over batch dim + state outputs
    softmax_dim0<<<H_, B_>>>(out);
    copy_out<<<(B_ * H_ + 255) / 256, 256>>>(out, out_size);
}